// round 1
// baseline (speedup 1.0000x reference)
#include <cuda_runtime.h>

// SNN: cur = x@w1^T once; then T=20 LIF steps, layer1 (4 neurons) -> dot w2 -> layer2 (1 neuron).
// Output spikes [T, B, 1] float32. Key identity: reset(t+1) == spike(t) (same m>THR predicate
// on the membrane that is unchanged between spike emission and next-step reset).

#define T_STEPS 20
#define BETA    0.9f
#define THR     1.0f

__global__ __launch_bounds__(256)
void snn_kernel(const float* __restrict__ x,
                const float* __restrict__ w1,   // [4,2] row-major
                const float* __restrict__ w2,   // [1,4]
                float* __restrict__ out,        // [T, B]
                int B)
{
    const int tid = blockIdx.x * blockDim.x + threadIdx.x;
    const int i0  = tid * 4;            // 4 batch elements per thread
    if (i0 >= B) return;

    // Broadcast weights (uniform across warp -> constant-like L1 hits)
    float w1v[8];
#pragma unroll
    for (int k = 0; k < 8; k++) w1v[k] = __ldg(w1 + k);
    float w2v[4];
#pragma unroll
    for (int k = 0; k < 4; k++) w2v[k] = __ldg(w2 + k);

    // Load x for 4 elements: 8 contiguous floats = 2x float4
    const float4* xv = reinterpret_cast<const float4*>(x + 2 * (size_t)i0);
    float4 xa = xv[0];
    float4 xb = xv[1];
    float xe[4][2] = {{xa.x, xa.y}, {xa.z, xa.w}, {xb.x, xb.y}, {xb.z, xb.w}};

    // cur[e][h] = x0*w1[h][0] + x1*w1[h][1]  (timestep-invariant)
    float cur[4][4];
#pragma unroll
    for (int e = 0; e < 4; e++)
#pragma unroll
        for (int h = 0; h < 4; h++)
            cur[e][h] = fmaf(xe[e][1], w1v[2 * h + 1], xe[e][0] * w1v[2 * h]);

    float m1[4][4], s1[4][4], m2[4], s2[4];
#pragma unroll
    for (int e = 0; e < 4; e++) {
#pragma unroll
        for (int h = 0; h < 4; h++) { m1[e][h] = 0.f; s1[e][h] = 0.f; }
        m2[e] = 0.f; s2[e] = 0.f;
    }

    float* outp = out + i0;
    const size_t stride = (size_t)B;

#pragma unroll 1   // keep the 20-step body small (I$), inner loops give ILP=16
    for (int t = 0; t < T_STEPS; t++) {
        float4 o;
        float* op = &o.x;
#pragma unroll
        for (int e = 0; e < 4; e++) {
            float acc = 0.f;
#pragma unroll
            for (int h = 0; h < 4; h++) {
                // reset = previous spike (0/1 float); mem = beta*mem + cur - reset*THR
                m1[e][h] = fmaf(BETA, m1[e][h], cur[e][h]) - s1[e][h];
                // spike = (mem > THR); also serves as next step's reset
                s1[e][h] = (m1[e][h] > THR) ? 1.f : 0.f;
                acc = fmaf(s1[e][h], w2v[h], acc);   // spk1 @ w2^T
            }
            m2[e] = fmaf(BETA, m2[e], acc) - s2[e];
            s2[e] = (m2[e] > THR) ? 1.f : 0.f;
            op[e] = s2[e];
        }
        *reinterpret_cast<float4*>(outp + (size_t)t * stride) = o;  // coalesced 128b
    }
}

extern "C" void kernel_launch(void* const* d_in, const int* in_sizes, int n_in,
                              void* d_out, int out_size)
{
    const float* x  = (const float*)d_in[0];   // [B,2]
    const float* w1 = (const float*)d_in[1];   // [4,2]
    const float* w2 = (const float*)d_in[2];   // [1,4]
    float* out = (float*)d_out;                // [T,B,1]

    const int B = in_sizes[0] / 2;             // 1,048,576
    const int elems_per_thread = 4;
    const int nthreads = (B + elems_per_thread - 1) / elems_per_thread;
    const int block = 256;
    const int grid = (nthreads + block - 1) / block;

    snn_kernel<<<grid, block>>>(x, w1, w2, out, B);
}

// round 2
// speedup vs baseline: 1.1099x; 1.1099x over previous
#include <cuda_runtime.h>

// SNN: cur = x@w1^T once; then T=20 LIF steps, layer1 (4 neurons) -> dot w2 -> layer2 (1 neuron).
// Issue-bound (ncu R1: issue=78.7%, dram=20%). This round: spike via PTX set.gt.f32.f32
// (SASS FSET.BF: one instruction producing 1.0f/0.0f) instead of FSETP+FSEL. All arithmetic
// ordering kept bit-identical to round 1 (rel_err must stay 8.6e-4).

#define T_STEPS 20
#define BETA    0.9f
#define THR     1.0f

// (a > b) ? 1.0f : 0.0f in (hopefully) ONE SASS instruction (FSET.BF.GT).
__device__ __forceinline__ float fset_gt(float a, float b) {
    float r;
    asm("set.gt.f32.f32 %0, %1, %2;" : "=f"(r) : "f"(a), "f"(b));
    return r;
}

__global__ __launch_bounds__(128)
void snn_kernel(const float* __restrict__ x,
                const float* __restrict__ w1,   // [4,2] row-major
                const float* __restrict__ w2,   // [1,4]
                float* __restrict__ out,        // [T, B]
                int B)
{
    const int tid = blockIdx.x * blockDim.x + threadIdx.x;
    const int i0  = tid * 4;            // 4 batch elements per thread
    if (i0 >= B) return;

    float w1v[8];
#pragma unroll
    for (int k = 0; k < 8; k++) w1v[k] = __ldg(w1 + k);
    float w2v[4];
#pragma unroll
    for (int k = 0; k < 4; k++) w2v[k] = __ldg(w2 + k);

    // Load x for 4 elements: 8 contiguous floats = 2x float4
    const float4* xv = reinterpret_cast<const float4*>(x + 2 * (size_t)i0);
    float4 xa = xv[0];
    float4 xb = xv[1];
    float xe[4][2] = {{xa.x, xa.y}, {xa.z, xa.w}, {xb.x, xb.y}, {xb.z, xb.w}};

    // cur[e][h] = x0*w1[h][0] + x1*w1[h][1]  (timestep-invariant) — identical to R1
    float cur[4][4];
#pragma unroll
    for (int e = 0; e < 4; e++)
#pragma unroll
        for (int h = 0; h < 4; h++)
            cur[e][h] = fmaf(xe[e][1], w1v[2 * h + 1], xe[e][0] * w1v[2 * h]);

    float m1[4][4], s1[4][4], m2[4], s2[4];
#pragma unroll
    for (int e = 0; e < 4; e++) {
#pragma unroll
        for (int h = 0; h < 4; h++) { m1[e][h] = 0.f; s1[e][h] = 0.f; }
        m2[e] = 0.f; s2[e] = 0.f;
    }

    float* outp = out + i0;
    const size_t stride = (size_t)B;

#pragma unroll 1   // keep the 20-step body small (I$); inner loops give ILP=16
    for (int t = 0; t < T_STEPS; t++) {
        float4 o;
        float* op = &o.x;
#pragma unroll
        for (int e = 0; e < 4; e++) {
            float acc = 0.f;
#pragma unroll
            for (int h = 0; h < 4; h++) {
                // mem = beta*mem + cur - reset (reset == previous spike, 0/1)
                m1[e][h] = fmaf(BETA, m1[e][h], cur[e][h]) - s1[e][h];
                // spike = (mem > THR) as 1.0/0.0 — single FSET.BF
                s1[e][h] = fset_gt(m1[e][h], THR);
                acc = fmaf(s1[e][h], w2v[h], acc);   // spk1 @ w2^T (same order as R1)
            }
            m2[e] = fmaf(BETA, m2[e], acc) - s2[e];
            s2[e] = fset_gt(m2[e], THR);
            op[e] = s2[e];
        }
        *reinterpret_cast<float4*>(outp + (size_t)t * stride) = o;  // coalesced 128b
    }
}

extern "C" void kernel_launch(void* const* d_in, const int* in_sizes, int n_in,
                              void* d_out, int out_size)
{
    const float* x  = (const float*)d_in[0];   // [B,2]
    const float* w1 = (const float*)d_in[1];   // [4,2]
    const float* w2 = (const float*)d_in[2];   // [1,4]
    float* out = (float*)d_out;                // [T,B,1]

    const int B = in_sizes[0] / 2;             // 1,048,576
    const int elems_per_thread = 4;
    const int nthreads = (B + elems_per_thread - 1) / elems_per_thread;
    const int block = 128;                     // finer CTA granularity for work-steal balance
    const int grid = (nthreads + block - 1) / block;

    snn_kernel<<<grid, block>>>(x, w1, w2, out, B);
}

// round 3
// speedup vs baseline: 1.2137x; 1.0935x over previous
#include <cuda_runtime.h>

// SNN XORNet: cur = x@w1^T once; T=20 LIF steps. Issue-slot bound (ncu: issue~78%,
// DRAM 21%). This round: pack pairs of batch elements into f32x2 (FFMA2, Blackwell
// packed fp32) — membrane update, reset-subtract and the spk1@w2 acc chain all become
// one instruction per 2 elements. Spike compare stays scalar (no packed f32 set).
// Every lane performs the identical IEEE op sequence as round 1 -> bit-identical output.

#define T_STEPS 20
#define BETA    0.9f
#define THR     1.0f

typedef unsigned long long u64;

__device__ __forceinline__ u64 pack2(float lo, float hi) {
    u64 r; asm("mov.b64 %0, {%1, %2};" : "=l"(r) : "f"(lo), "f"(hi)); return r;
}
__device__ __forceinline__ void unpack2(u64 v, float& lo, float& hi) {
    asm("mov.b64 {%0, %1}, %2;" : "=f"(lo), "=f"(hi) : "l"(v));
}
// two fp32 FMAs in one SASS instruction (FFMA2)
__device__ __forceinline__ u64 fma2(u64 a, u64 b, u64 c) {
    u64 r; asm("fma.rn.f32x2 %0, %1, %2, %3;" : "=l"(r) : "l"(a), "l"(b), "l"(c)); return r;
}
// (a > b) ? 1.0f : 0.0f
__device__ __forceinline__ float fset_gt(float a, float b) {
    float r; asm("set.gt.f32.f32 %0, %1, %2;" : "=f"(r) : "f"(a), "f"(b)); return r;
}

__global__ __launch_bounds__(128)
void snn_kernel(const float* __restrict__ x,
                const float* __restrict__ w1,   // [4,2]
                const float* __restrict__ w2,   // [1,4]
                float* __restrict__ out,        // [T, B]
                int B)
{
    const int tid = blockIdx.x * blockDim.x + threadIdx.x;
    const int i0  = tid * 4;                    // 4 batch elements = 2 f32x2 pairs
    if (i0 >= B) return;

    float w1v[8];
#pragma unroll
    for (int k = 0; k < 8; k++) w1v[k] = __ldg(w1 + k);
    u64 w2p[4];
#pragma unroll
    for (int k = 0; k < 4; k++) { float w = __ldg(w2 + k); w2p[k] = pack2(w, w); }

    const u64 BETA2 = pack2(BETA, BETA);
    const u64 NEG1  = pack2(-1.f, -1.f);

    // x for 4 elements: 8 contiguous floats
    const float4* xv = reinterpret_cast<const float4*>(x + 2 * (size_t)i0);
    float4 xa = xv[0];
    float4 xb = xv[1];
    float xe[4][2] = {{xa.x, xa.y}, {xa.z, xa.w}, {xb.x, xb.y}, {xb.z, xb.w}};

    // cur packed per pair: lane0=elem(2p), lane1=elem(2p+1). Same scalar math as R1.
    u64 cur2[2][4];
#pragma unroll
    for (int p = 0; p < 2; p++)
#pragma unroll
        for (int h = 0; h < 4; h++) {
            float c0 = fmaf(xe[2*p  ][1], w1v[2*h+1], xe[2*p  ][0] * w1v[2*h]);
            float c1 = fmaf(xe[2*p+1][1], w1v[2*h+1], xe[2*p+1][0] * w1v[2*h]);
            cur2[p][h] = pack2(c0, c1);
        }

    u64 m1[2][4], s1[2][4], m2[2], s2[2];
#pragma unroll
    for (int p = 0; p < 2; p++) {
#pragma unroll
        for (int h = 0; h < 4; h++) { m1[p][h] = 0ull; s1[p][h] = 0ull; }
        m2[p] = 0ull; s2[p] = 0ull;
    }

    float* outp = out + i0;
    const size_t stride = (size_t)B;

#pragma unroll 1   // rolled T loop: small body (I$), inner unroll gives ILP
    for (int t = 0; t < T_STEPS; t++) {
        float4 o;
        float* op = &o.x;
#pragma unroll
        for (int p = 0; p < 2; p++) {
            u64 acc = 0ull;                       // {0.f, 0.f}
#pragma unroll
            for (int h = 0; h < 4; h++) {
                // m = beta*m + cur   (FFMA2)
                m1[p][h] = fma2(BETA2, m1[p][h], cur2[p][h]);
                // m = m - s_prev  == fma(s, -1, m), exact, single rounding (FFMA2)
                m1[p][h] = fma2(s1[p][h], NEG1, m1[p][h]);
                float lo, hi; unpack2(m1[p][h], lo, hi);
                float slo = fset_gt(lo, THR);
                float shi = fset_gt(hi, THR);
                s1[p][h] = pack2(slo, shi);
                // acc += spk * w2[h]  (FFMA2)
                acc = fma2(s1[p][h], w2p[h], acc);
            }
            m2[p] = fma2(BETA2, m2[p], acc);
            m2[p] = fma2(s2[p], NEG1, m2[p]);
            float lo, hi; unpack2(m2[p], lo, hi);
            float slo = fset_gt(lo, THR);
            float shi = fset_gt(hi, THR);
            s2[p] = pack2(slo, shi);
            op[2*p]   = slo;
            op[2*p+1] = shi;
        }
        *reinterpret_cast<float4*>(outp + (size_t)t * stride) = o;  // coalesced 128b
    }
}

extern "C" void kernel_launch(void* const* d_in, const int* in_sizes, int n_in,
                              void* d_out, int out_size)
{
    const float* x  = (const float*)d_in[0];   // [B,2]
    const float* w1 = (const float*)d_in[1];   // [4,2]
    const float* w2 = (const float*)d_in[2];   // [1,4]
    float* out = (float*)d_out;                // [T,B,1]

    const int B = in_sizes[0] / 2;             // 1,048,576
    const int elems_per_thread = 4;
    const int nthreads = (B + elems_per_thread - 1) / elems_per_thread;
    const int block = 128;
    const int grid = (nthreads + block - 1) / block;

    snn_kernel<<<grid, block>>>(x, w1, w2, out, B);
}